// round 14
// baseline (speedup 1.0000x reference)
#include <cuda_runtime.h>
#include <cuda_fp16.h>
#include <cstdint>

#define BATCH 4096
#define T_STEPS 50
#define HID 256
#define HSTR (T_STEPS * HID)   // out row stride: 12800 floats

// ---------------- scratch (no allocations allowed) ----------------
__device__ float g_xhi[BATCH * 256],  g_xlo[BATCH * 256];
__device__ float g_w1h[512 * 256],    g_w1l[512 * 256];
__device__ float g_w2h[256 * 512],    g_w2l[256 * 512];
__device__ float g_w3h[128 * 256],    g_w3l[128 * 256];
__device__ float g_wihh[1024 * 128],  g_wihl[1024 * 128];   // rows permuted n=4j+g
__device__ float g_biasp[1024];                              // permuted b_ih+b_hh
__device__ float g_h1h[BATCH * 512],  g_h1l[BATCH * 512];
__device__ float g_h2h[BATCH * 256],  g_h2l[BATCH * 256];
__device__ float g_z1h[BATCH * 128],  g_z1l[BATCH * 128];
__device__ __half g_xpp[BATCH * 1024];       // fp16 x_part [4096][1024], n=4j+g (incl biases)
__device__ __half g_whhc[1024 * 256];        // fp16 Whh rows permuted n=4j+g

// ---------------- helpers ----------------
__device__ __forceinline__ uint32_t f2tf(float x) {
    uint32_t r;
    asm("cvt.rna.tf32.f32 %0, %1;" : "=r"(r) : "f"(x));
    return r;
}
__device__ __forceinline__ float f2tf_f(float x) { return __uint_as_float(f2tf(x)); }
__device__ __forceinline__ uint32_t smem_u32(const void* p) {
    uint32_t a;
    asm("{ .reg .u64 t; cvta.to.shared.u64 t, %1; cvt.u32.u64 %0, t; }" : "=r"(a) : "l"(p));
    return a;
}
__device__ __forceinline__ void cp16(uint32_t d, const void* s) {
    asm volatile("cp.async.cg.shared.global [%0], [%1], 16;" :: "r"(d), "l"(s));
}
__device__ __forceinline__ void cp_commit() { asm volatile("cp.async.commit_group;"); }
__device__ __forceinline__ void cp_wait1()  { asm volatile("cp.async.wait_group 1;" ::: "memory"); }
__device__ __forceinline__ void cp_wait0()  { asm volatile("cp.async.wait_group 0;" ::: "memory"); }
__device__ __forceinline__ void mma8(float* c, const uint32_t* a, const uint32_t* b) {
    asm volatile(
        "mma.sync.aligned.m16n8k8.row.col.f32.tf32.tf32.f32 "
        "{%0,%1,%2,%3}, {%4,%5,%6,%7}, {%8,%9}, {%0,%1,%2,%3};"
        : "+f"(c[0]), "+f"(c[1]), "+f"(c[2]), "+f"(c[3])
        : "r"(a[0]), "r"(a[1]), "r"(a[2]), "r"(a[3]), "r"(b[0]), "r"(b[1]));
}
__device__ __forceinline__ void mma16(float* c, const uint32_t* a, const uint32_t* b) {
    asm volatile(
        "mma.sync.aligned.m16n8k16.row.col.f32.f16.f16.f32 "
        "{%0,%1,%2,%3}, {%4,%5,%6,%7}, {%8,%9}, {%0,%1,%2,%3};"
        : "+f"(c[0]), "+f"(c[1]), "+f"(c[2]), "+f"(c[3])
        : "r"(a[0]), "r"(a[1]), "r"(a[2]), "r"(a[3]), "r"(b[0]), "r"(b[1]));
}
__device__ __forceinline__ float sigmoidf_fast(float x) {
    return __fdividef(1.0f, 1.0f + __expf(-x));
}
__device__ __forceinline__ float tanhf_fast(float x) {
    return fmaf(2.0f, __fdividef(1.0f, 1.0f + __expf(-2.0f * x)), -1.0f);
}

// ---------------- setup kernels ----------------
__global__ void conv_all(const float* __restrict__ zs, const float* __restrict__ W1,
                         const float* __restrict__ W2, const float* __restrict__ W3) {
    int i = blockIdx.x * 256 + threadIdx.x;
    const float* s; float *hi, *lo; int off;
    if      (i < 1048576) { s = zs;  hi = g_xhi;  lo = g_xlo;  off = i; }
    else if (i < 1179648) { s = W1;  hi = g_w1h;  lo = g_w1l;  off = i - 1048576; }
    else if (i < 1310720) { s = W2;  hi = g_w2h;  lo = g_w2l;  off = i - 1179648; }
    else if (i < 1343488) { s = W3;  hi = g_w3h;  lo = g_w3l;  off = i - 1310720; }
    else return;
    float x = s[off];
    float h = f2tf_f(x);
    hi[off] = h;
    lo[off] = f2tf_f(x - h);
}
// permuted n = 4j + g  <-  gate row gr = g*256 + j
__global__ void conv_wih_p(const float* __restrict__ wih, const float* __restrict__ bih,
                           const float* __restrict__ bhh) {
    int k = threadIdx.x, n = blockIdx.x;        // k 0..127, n 0..1023
    int gr = (n & 3) * 256 + (n >> 2);
    float x = wih[(size_t)gr * 128 + k];
    float h = f2tf_f(x);
    g_wihh[n * 128 + k] = h;
    g_wihl[n * 128 + k] = f2tf_f(x - h);
    if (k == 0) g_biasp[n] = bih[gr] + bhh[gr];
}
__global__ void conv_whh_p(const float* __restrict__ whh) {
    int k = threadIdx.x, n = blockIdx.x;        // k 0..255
    int gr = (n & 3) * 256 + (n >> 2);
    g_whhc[n * 256 + k] = __float2half(whh[(size_t)gr * 256 + k]);
}

// ================= split-tf32 GEMM (MLP), 256 threads, 128x128 tile =========
#define SG_STRIDE 36
#define SG_HALF   (128 * SG_STRIDE * 4)   // 18432
#define SG_STAGE  (4 * SG_HALF)           // 73728
#define SG_SMEM   (3 * SG_STAGE)          // 221184
#define SG_GS     133

__device__ __forceinline__ void sg_issue(char* sm, int st,
    const float* Ahi, const float* Alo, const float* Bhi, const float* Blo,
    int aBase, int bBase, int K, int tid)
{
    uint32_t base = smem_u32(sm + (st % 3) * SG_STAGE);
    const int k0 = st * 32;
    const int srow = tid >> 3, sk4 = (tid & 7) << 2;
    #pragma unroll
    for (int i = 0; i < 4; i++) {
        int row = i * 32 + srow;
        uint32_t d = base + (uint32_t)(row * SG_STRIDE + sk4) * 4;
        size_t ao = (size_t)(aBase + row) * K + k0 + sk4;
        size_t bo = (size_t)(bBase + row) * K + k0 + sk4;
        cp16(d,               Ahi + ao);
        cp16(d + SG_HALF,     Alo + ao);
        cp16(d + 2 * SG_HALF, Bhi + bo);
        cp16(d + 3 * SG_HALF, Blo + bo);
    }
    cp_commit();
}

// out modes: Clo!=null -> split hi/lo fp32; else out16 -> fp16 [row][col]; else fp32
__global__ void __launch_bounds__(256, 1) mma_gemm_split(
    const float* __restrict__ Ahi, const float* __restrict__ Alo,
    const float* __restrict__ Bhi, const float* __restrict__ Blo,
    const float* __restrict__ bias,
    float* __restrict__ Chi, float* __restrict__ Clo,
    int M, int N, int K, int relu, int out16)
{
    extern __shared__ char sm[];
    const int tid = threadIdx.x;
    const int wid = tid >> 5, lane = tid & 31;
    const int wm = wid & 3, wn = wid >> 2;
    const int bm = blockIdx.y * 128, bn = blockIdx.x * 128;
    const int NC = K >> 5;

    float acc[2][8][4];
    #pragma unroll
    for (int mi = 0; mi < 2; mi++)
        #pragma unroll
        for (int ni = 0; ni < 8; ni++)
            #pragma unroll
            for (int v = 0; v < 4; v++) acc[mi][ni][v] = 0.0f;

    sg_issue(sm, 0, Ahi, Alo, Bhi, Blo, bm, bn, K, tid);
    sg_issue(sm, 1, Ahi, Alo, Bhi, Blo, bm, bn, K, tid);

    const int ar = wm * 32 + (lane >> 2);
    const int bc = wn * 64 + (lane >> 2);
    const int q  = lane & 3;

    #pragma unroll 1
    for (int ch = 0; ch < NC; ch++) {
        if (ch == NC - 1) cp_wait0(); else cp_wait1();
        __syncthreads();
        if (ch + 2 < NC) sg_issue(sm, ch + 2, Ahi, Alo, Bhi, Blo, bm, bn, K, tid);
        const uint32_t* Ah = (const uint32_t*)(sm + (ch % 3) * SG_STAGE);
        const uint32_t* Al = Ah + SG_HALF / 4;
        const uint32_t* Bh = Ah + 2 * SG_HALF / 4;
        const uint32_t* Bl = Ah + 3 * SG_HALF / 4;
        #pragma unroll
        for (int kk = 0; kk < 4; kk++) {
            const int kb = kk * 8 + q;
            uint32_t ah[2][4], al[2][4], bh[8][2], bl[8][2];
            #pragma unroll
            for (int mi = 0; mi < 2; mi++) {
                const int r0 = (ar + mi * 16) * SG_STRIDE;
                const int r8 = (ar + mi * 16 + 8) * SG_STRIDE;
                ah[mi][0] = Ah[r0 + kb]; ah[mi][1] = Ah[r8 + kb];
                ah[mi][2] = Ah[r0 + kb + 4]; ah[mi][3] = Ah[r8 + kb + 4];
                al[mi][0] = Al[r0 + kb]; al[mi][1] = Al[r8 + kb];
                al[mi][2] = Al[r0 + kb + 4]; al[mi][3] = Al[r8 + kb + 4];
            }
            #pragma unroll
            for (int ni = 0; ni < 8; ni++) {
                const int rB = (bc + ni * 8) * SG_STRIDE;
                bh[ni][0] = Bh[rB + kb]; bh[ni][1] = Bh[rB + kb + 4];
                bl[ni][0] = Bl[rB + kb]; bl[ni][1] = Bl[rB + kb + 4];
            }
            #pragma unroll
            for (int mi = 0; mi < 2; mi++)
                #pragma unroll
                for (int ni = 0; ni < 8; ni++) {
                    mma8(acc[mi][ni], ah[mi], bl[ni]);
                    mma8(acc[mi][ni], al[mi], bh[ni]);
                    mma8(acc[mi][ni], ah[mi], bh[ni]);
                }
        }
    }
    __syncthreads();

    {
        float* gs = (float*)sm;
        const int grow = wm * 32 + (lane >> 2);
        const int gcol = wn * 64 + ((lane & 3) << 1);
        #pragma unroll
        for (int mi = 0; mi < 2; mi++)
            #pragma unroll
            for (int ni = 0; ni < 8; ni++) {
                int r = grow + mi * 16, cc = gcol + ni * 8;
                gs[r * SG_GS + cc]           = acc[mi][ni][0];
                gs[r * SG_GS + cc + 1]       = acc[mi][ni][1];
                gs[(r + 8) * SG_GS + cc]     = acc[mi][ni][2];
                gs[(r + 8) * SG_GS + cc + 1] = acc[mi][ni][3];
            }
    }
    __syncthreads();

    const float* gs = (const float*)sm;
    #pragma unroll
    for (int i = 0; i < 16; i++) {
        int row = i * 8 + wid;
        #pragma unroll
        for (int cc = 0; cc < 4; cc++) {
            int col = cc * 32 + lane;
            float v = gs[row * SG_GS + col] + bias[bn + col];
            if (relu) v = fmaxf(v, 0.0f);
            size_t o = (size_t)(bm + row) * N + bn + col;
            if (Clo) {
                float h = f2tf_f(v);
                Chi[o] = h;
                Clo[o] = f2tf_f(v - h);
            } else if (out16) {
                ((__half*)Chi)[o] = __float2half(v);
            } else {
                Chi[o] = v;
            }
        }
    }
}

// ============ persistent row-local LSTM: 128 CTAs, NO cross-CTA deps ========
// CTA owns 32 batch rows. gates[32][1024] = h[32,256](fp16, smem) @ Whh^T(fp16,
// streamed from L2). n = 4j+g layout -> all 4 gates of hidden j in one warp;
// shfl.xor(1) pair-exchange completes each cell in registers (no gate staging).
// h, c, xp resident in smem for all 50 steps.
#define PA_OFF  0                         // h/A: 32 rows x 132 words (264 halves)
#define PA_SZ   (32 * 132 * 4)            // 16896
#define PX_OFF  PA_SZ                     // xp: 32 rows x 1048 halves
#define PX_W    524                       // xp row stride in words
#define PX_SZ   (32 * PX_W * 4)           // 67072
#define PC_OFF  (PX_OFF + PX_SZ)          // c: 32 x 257 fp32
#define PC_SZ   (32 * 257 * 4)            // 32896
#define PB0_OFF (PC_OFF + PC_SZ)          // 116864
#define PB_SZ   (1024 * 12 * 4)           // 49152 per chunk buffer
#define PB1_OFF (PB0_OFF + PB_SZ)         // 166016 (also hs fp32, stride 257)
#define P_SMEM  (PB1_OFF + PB_SZ)         // 215168

__device__ __forceinline__ void pb_issue(uint32_t buf, int ch, int tid) {
    // chunk ch: 1024 rows x 16 halves (32 B) -> 2048 cp16
    #pragma unroll
    for (int i = 0; i < 4; i++) {
        int idx = i * 512 + tid;
        int n = idx >> 1, part = idx & 1;
        cp16(buf + (uint32_t)(n * 48 + part * 16),
             g_whhc + (size_t)n * 256 + ch * 16 + part * 8);
    }
    cp_commit();
}

__global__ void __launch_bounds__(512, 1)
lstm_persist(float* __restrict__ out)
{
    extern __shared__ char sm[];
    const int tid  = threadIdx.x;
    const int wid  = tid >> 5;
    const int lane = tid & 31;
    const int wn   = wid;                 // warp n-tile: cols [64*wn, 64*wn+64)
    const int bm   = blockIdx.x * 32;
    const int r    = lane >> 2;
    const int q    = lane & 3;
    const int odd  = q & 1;

    uint32_t sb = smem_u32(sm);
    const uint32_t* As = (const uint32_t*)(sm + PA_OFF);
    __half* Ah = (__half*)(sm + PA_OFF);
    const __half* xps = (const __half*)(sm + PX_OFF);
    float* csm = (float*)(sm + PC_OFF);
    float* hs  = (float*)(sm + PB1_OFF);

    // ---- load xp slice once: 32 rows x 1024 halves ----
    #pragma unroll
    for (int i = 0; i < 8; i++) {
        int idx = i * 512 + tid;
        int row = idx >> 7, off8 = (idx & 127) * 8;
        cp16(sb + PX_OFF + (uint32_t)(row * PX_W * 4 + off8 * 2),
             g_xpp + (size_t)(bm + row) * 1024 + off8);
    }
    cp_commit(); cp_wait0();
    __syncthreads();

    #pragma unroll 1
    for (int t = 0; t < T_STEPS; t++) {
        float acc[2][8][4];
        #pragma unroll
        for (int mi = 0; mi < 2; mi++)
            #pragma unroll
            for (int ni = 0; ni < 8; ni++)
                #pragma unroll
                for (int v = 0; v < 4; v++) acc[mi][ni][v] = 0.0f;

        if (t > 0) {
            #pragma unroll 1
            for (int ch = 0; ch < 16; ch++) {
                if (ch == 15) cp_wait0(); else cp_wait1();
                __syncthreads();
                const uint32_t* Bs = (const uint32_t*)(sm + ((ch & 1) ? PB1_OFF : PB0_OFF));
                uint32_t a[2][4], b[8][2];
                #pragma unroll
                for (int mi = 0; mi < 2; mi++) {
                    const int r0 = (16 * mi + r) * 132 + 8 * ch + q;
                    const int r8 = r0 + 8 * 132;
                    a[mi][0] = As[r0];     a[mi][1] = As[r8];
                    a[mi][2] = As[r0 + 4]; a[mi][3] = As[r8 + 4];
                }
                #pragma unroll
                for (int ni = 0; ni < 8; ni++) {
                    const int rB = (64 * wn + 8 * ni + r) * 12 + q;
                    b[ni][0] = Bs[rB];
                    b[ni][1] = Bs[rB + 4];
                }
                #pragma unroll
                for (int mi = 0; mi < 2; mi++)
                    #pragma unroll
                    for (int ni = 0; ni < 8; ni++)
                        mma16(acc[mi][ni], a[mi], b[ni]);
                __syncthreads();
                if (ch + 2 < 16)
                    pb_issue(sb + ((ch & 1) ? PB1_OFF : PB0_OFF), ch + 2, tid);
            }
        }
        // buffers free; prefetch next-step chunk 0 into B0 (overlaps epilogue)
        if (t < T_STEPS - 1) pb_issue(sb + PB0_OFF, 0, tid);

        // ---- register epilogue: shfl pair-exchange, full cell per thread ----
        #pragma unroll
        for (int mi = 0; mi < 2; mi++)
            #pragma unroll
            for (int ni = 0; ni < 8; ni++) {
                float t0 = odd ? acc[mi][ni][0] : acc[mi][ni][2];
                float t1 = odd ? acc[mi][ni][1] : acc[mi][ni][3];
                float e0 = __shfl_xor_sync(0xffffffffu, t0, 1);
                float e1 = __shfl_xor_sync(0xffffffffu, t1, 1);
                float gi, gf, gg, go;
                if (!odd) { gi = acc[mi][ni][0]; gf = acc[mi][ni][1]; gg = e0; go = e1; }
                else      { gi = e0; gf = e1; gg = acc[mi][ni][2]; go = acc[mi][ni][3]; }
                const int row = 16 * mi + r + 8 * odd;
                const int j   = 16 * wn + 2 * ni + (q >> 1);
                // xp: 4 consecutive halves (gates) at n = 4j
                uint2 xv = *(const uint2*)(xps + row * (PX_W * 2) + 4 * j);
                __half2 x01 = *(__half2*)&xv.x;
                __half2 x23 = *(__half2*)&xv.y;
                gi += __low2float(x01);  gf += __high2float(x01);
                gg += __low2float(x23);  go += __high2float(x23);
                float cp = (t > 0) ? csm[row * 257 + j] : 0.0f;
                float vi = sigmoidf_fast(gi);
                float vf = sigmoidf_fast(gf);
                float vg = tanhf_fast(gg);
                float vo = sigmoidf_fast(go);
                float cn = vf * cp + vi * vg;
                csm[row * 257 + j] = cn;
                float hv = vo * tanhf_fast(cn);
                hs[row * 257 + j] = hv;               // fp32 for out
                Ah[row * 264 + j] = __float2half(hv); // fp16 for next GEMM
            }
        __syncthreads();

        // ---- coalesced out write from hs ----
        {
            const int row0 = wid * 2;
            #pragma unroll
            for (int rr = 0; rr < 2; rr++) {
                const int row = row0 + rr;
                float* orow = out + (size_t)(bm + row) * HSTR + (size_t)t * HID;
                #pragma unroll
                for (int i = 0; i < 8; i++)
                    orow[i * 32 + lane] = hs[row * 257 + i * 32 + lane];
            }
        }
        __syncthreads();
        // hs region free again; prefetch chunk 1 into B1
        if (t < T_STEPS - 1) pb_issue(sb + PB1_OFF, 1, tid);
    }
}

// ---------------- launch ----------------
extern "C" void kernel_launch(void* const* d_in, const int* in_sizes, int n_in,
                              void* d_out, int out_size)
{
    const float* zs  = (const float*)d_in[0];
    const float* W1  = (const float*)d_in[1];
    const float* b1  = (const float*)d_in[2];
    const float* W2  = (const float*)d_in[3];
    const float* b2  = (const float*)d_in[4];
    const float* W3  = (const float*)d_in[5];
    const float* b3  = (const float*)d_in[6];
    const float* Wih = (const float*)d_in[7];
    const float* Whh = (const float*)d_in[8];
    const float* bih = (const float*)d_in[9];
    const float* bhh = (const float*)d_in[10];
    float* out = (float*)d_out;

    float *xhi, *xlo, *w1h, *w1l, *w2h, *w2l, *w3h, *w3l, *wihh, *wihl, *biasp;
    float *h1h, *h1l, *h2h, *h2l, *z1h, *z1l;
    void  *xpp;
    cudaGetSymbolAddress((void**)&xhi,   g_xhi);
    cudaGetSymbolAddress((void**)&xlo,   g_xlo);
    cudaGetSymbolAddress((void**)&w1h,   g_w1h);
    cudaGetSymbolAddress((void**)&w1l,   g_w1l);
    cudaGetSymbolAddress((void**)&w2h,   g_w2h);
    cudaGetSymbolAddress((void**)&w2l,   g_w2l);
    cudaGetSymbolAddress((void**)&w3h,   g_w3h);
    cudaGetSymbolAddress((void**)&w3l,   g_w3l);
    cudaGetSymbolAddress((void**)&wihh,  g_wihh);
    cudaGetSymbolAddress((void**)&wihl,  g_wihl);
    cudaGetSymbolAddress((void**)&biasp, g_biasp);
    cudaGetSymbolAddress((void**)&h1h,   g_h1h);
    cudaGetSymbolAddress((void**)&h1l,   g_h1l);
    cudaGetSymbolAddress((void**)&h2h,   g_h2h);
    cudaGetSymbolAddress((void**)&h2l,   g_h2l);
    cudaGetSymbolAddress((void**)&z1h,   g_z1h);
    cudaGetSymbolAddress((void**)&z1l,   g_z1l);
    cudaGetSymbolAddress(&xpp,           g_xpp);

    cudaFuncSetAttribute(mma_gemm_split,
                         cudaFuncAttributeMaxDynamicSharedMemorySize, SG_SMEM);
    cudaFuncSetAttribute(lstm_persist,
                         cudaFuncAttributeMaxDynamicSharedMemorySize, P_SMEM);

    // setup
    conv_all<<<5248, 256>>>(zs, W1, W2, W3);
    conv_wih_p<<<1024, 128>>>(Wih, bih, bhh);
    conv_whh_p<<<1024, 256>>>(Whh);

    // MLP (split-tf32, fp32-grade accuracy)
    mma_gemm_split<<<dim3(4, 32), 256, SG_SMEM>>>(xhi, xlo, w1h, w1l, b1,
                                                  h1h, h1l, BATCH, 512, 256, 1, 0);
    mma_gemm_split<<<dim3(2, 32), 256, SG_SMEM>>>(h1h, h1l, w2h, w2l, b2,
                                                  h2h, h2l, BATCH, 256, 512, 1, 0);
    mma_gemm_split<<<dim3(1, 32), 256, SG_SMEM>>>(h2h, h2l, w3h, w3l, b3,
                                                  z1h, z1l, BATCH, 128, 256, 0, 0);
    // x_part fp16 [4096][1024], n = 4j+g (biases folded)
    mma_gemm_split<<<dim3(8, 32), 256, SG_SMEM>>>(z1h, z1l, wihh, wihl, biasp,
                                                  (float*)xpp, nullptr,
                                                  BATCH, 1024, 128, 0, 1);

    // all 50 LSTM steps: one persistent launch, zero cross-CTA dependencies
    lstm_persist<<<128, 512, P_SMEM>>>(out);
}

// round 17
// speedup vs baseline: 1.4818x; 1.4818x over previous
#include <cuda_runtime.h>
#include <cuda_fp16.h>
#include <cstdint>

#define BATCH 4096
#define T_STEPS 50
#define HID 256
#define HSTR (T_STEPS * HID)   // out row stride: 12800 floats

// ---------------- scratch (no allocations allowed) ----------------
__device__ float g_xhi[BATCH * 256],  g_xlo[BATCH * 256];
__device__ float g_w1h[512 * 256],    g_w1l[512 * 256];
__device__ float g_w2h[256 * 512],    g_w2l[256 * 512];
__device__ float g_w3h[128 * 256],    g_w3l[128 * 256];
__device__ float g_wihh[1024 * 128],  g_wihl[1024 * 128];   // rows permuted n=4j+g
__device__ float g_biasp[1024];                              // permuted b_ih+b_hh
__device__ float g_h1h[BATCH * 512],  g_h1l[BATCH * 512];
__device__ float g_h2h[BATCH * 256],  g_h2l[BATCH * 256];
__device__ float g_z1h[BATCH * 128],  g_z1l[BATCH * 128];
__device__ __half g_xpp[BATCH * 1024];       // fp16 x_part [4096][1024], col = 4j+g (biases in)
__device__ float g_c [256  * BATCH];         // fp32 TRANSPOSED [256][4096]
__device__ __half g_ht[BATCH * 256];         // fp16 compact h_{t-1}
__device__ __half g_whhc[1024 * 256];        // fp16 Whh rows permuted: r' = jb8*128 + 4*jloc + g

// ---------------- helpers ----------------
__device__ __forceinline__ uint32_t f2tf(float x) {
    uint32_t r;
    asm("cvt.rna.tf32.f32 %0, %1;" : "=r"(r) : "f"(x));
    return r;
}
__device__ __forceinline__ float f2tf_f(float x) { return __uint_as_float(f2tf(x)); }
__device__ __forceinline__ uint32_t smem_u32(const void* p) {
    uint32_t a;
    asm("{ .reg .u64 t; cvta.to.shared.u64 t, %1; cvt.u32.u64 %0, t; }" : "=r"(a) : "l"(p));
    return a;
}
__device__ __forceinline__ void cp16(uint32_t d, const void* s) {
    asm volatile("cp.async.cg.shared.global [%0], [%1], 16;" :: "r"(d), "l"(s));
}
__device__ __forceinline__ void cp_commit() { asm volatile("cp.async.commit_group;"); }
__device__ __forceinline__ void cp_wait1()  { asm volatile("cp.async.wait_group 1;" ::: "memory"); }
__device__ __forceinline__ void cp_wait0()  { asm volatile("cp.async.wait_group 0;" ::: "memory"); }
__device__ __forceinline__ void mma8(float* c, const uint32_t* a, const uint32_t* b) {
    asm volatile(
        "mma.sync.aligned.m16n8k8.row.col.f32.tf32.tf32.f32 "
        "{%0,%1,%2,%3}, {%4,%5,%6,%7}, {%8,%9}, {%0,%1,%2,%3};"
        : "+f"(c[0]), "+f"(c[1]), "+f"(c[2]), "+f"(c[3])
        : "r"(a[0]), "r"(a[1]), "r"(a[2]), "r"(a[3]), "r"(b[0]), "r"(b[1]));
}
__device__ __forceinline__ void mma16(float* c, const uint32_t* a, const uint32_t* b) {
    asm volatile(
        "mma.sync.aligned.m16n8k16.row.col.f32.f16.f16.f32 "
        "{%0,%1,%2,%3}, {%4,%5,%6,%7}, {%8,%9}, {%0,%1,%2,%3};"
        : "+f"(c[0]), "+f"(c[1]), "+f"(c[2]), "+f"(c[3])
        : "r"(a[0]), "r"(a[1]), "r"(a[2]), "r"(a[3]), "r"(b[0]), "r"(b[1]));
}
__device__ __forceinline__ float sigmoidf_fast(float x) {
    return __fdividef(1.0f, 1.0f + __expf(-x));
}
__device__ __forceinline__ float tanhf_fast(float x) {
    return fmaf(2.0f, __fdividef(1.0f, 1.0f + __expf(-2.0f * x)), -1.0f);
}

// ---------------- setup kernels ----------------
__global__ void conv_all(const float* __restrict__ zs, const float* __restrict__ W1,
                         const float* __restrict__ W2, const float* __restrict__ W3) {
    int i = blockIdx.x * 256 + threadIdx.x;
    const float* s; float *hi, *lo; int off;
    if      (i < 1048576) { s = zs;  hi = g_xhi;  lo = g_xlo;  off = i; }
    else if (i < 1179648) { s = W1;  hi = g_w1h;  lo = g_w1l;  off = i - 1048576; }
    else if (i < 1310720) { s = W2;  hi = g_w2h;  lo = g_w2l;  off = i - 1179648; }
    else if (i < 1343488) { s = W3;  hi = g_w3h;  lo = g_w3l;  off = i - 1310720; }
    else return;
    float x = s[off];
    float h = f2tf_f(x);
    hi[off] = h;
    lo[off] = f2tf_f(x - h);
}
// Wih rows permuted n = 4j + g  <-  gate row gr = g*256 + j ; biases folded
__global__ void conv_wih_p(const float* __restrict__ wih, const float* __restrict__ bih,
                           const float* __restrict__ bhh) {
    int k = threadIdx.x, n = blockIdx.x;        // k 0..127, n 0..1023
    int gr = (n & 3) * 256 + (n >> 2);
    float x = wih[(size_t)gr * 128 + k];
    float h = f2tf_f(x);
    g_wihh[n * 128 + k] = h;
    g_wihl[n * 128 + k] = f2tf_f(x - h);
    if (k == 0) g_biasp[n] = bih[gr] + bhh[gr];
}
// Whh rows permuted: r' = jb8*128 + 4*jloc + g  <-  gr = g*256 + jb8*32 + jloc
__global__ void conv_whh_p(const float* __restrict__ whh) {
    int k = threadIdx.x, rp = blockIdx.x;       // rp 0..1023
    int jb8 = rp >> 7, n = rp & 127;
    int jloc = n >> 2, g = n & 3;
    int gr = g * 256 + jb8 * 32 + jloc;
    g_whhc[rp * 256 + k] = __float2half(whh[(size_t)gr * 256 + k]);
}

// ================= split-tf32 GEMM (MLP), 256 threads, 128x128 tile =========
#define SG_STRIDE 36
#define SG_HALF   (128 * SG_STRIDE * 4)   // 18432
#define SG_STAGE  (4 * SG_HALF)           // 73728
#define SG_SMEM   (3 * SG_STAGE)          // 221184
#define SG_GS     133

__device__ __forceinline__ void sg_issue(char* sm, int st,
    const float* Ahi, const float* Alo, const float* Bhi, const float* Blo,
    int aBase, int bBase, int K, int tid)
{
    uint32_t base = smem_u32(sm + (st % 3) * SG_STAGE);
    const int k0 = st * 32;
    const int srow = tid >> 3, sk4 = (tid & 7) << 2;
    #pragma unroll
    for (int i = 0; i < 4; i++) {
        int row = i * 32 + srow;
        uint32_t d = base + (uint32_t)(row * SG_STRIDE + sk4) * 4;
        size_t ao = (size_t)(aBase + row) * K + k0 + sk4;
        size_t bo = (size_t)(bBase + row) * K + k0 + sk4;
        cp16(d,               Ahi + ao);
        cp16(d + SG_HALF,     Alo + ao);
        cp16(d + 2 * SG_HALF, Bhi + bo);
        cp16(d + 3 * SG_HALF, Blo + bo);
    }
    cp_commit();
}

// out modes: Clo!=null -> split hi/lo fp32; else out16 -> fp16 row-major; else fp32
__global__ void __launch_bounds__(256, 1) mma_gemm_split(
    const float* __restrict__ Ahi, const float* __restrict__ Alo,
    const float* __restrict__ Bhi, const float* __restrict__ Blo,
    const float* __restrict__ bias,
    float* __restrict__ Chi, float* __restrict__ Clo,
    int M, int N, int K, int relu, int out16)
{
    extern __shared__ char sm[];
    const int tid = threadIdx.x;
    const int wid = tid >> 5, lane = tid & 31;
    const int wm = wid & 3, wn = wid >> 2;
    const int bm = blockIdx.y * 128, bn = blockIdx.x * 128;
    const int NC = K >> 5;

    float acc[2][8][4];
    #pragma unroll
    for (int mi = 0; mi < 2; mi++)
        #pragma unroll
        for (int ni = 0; ni < 8; ni++)
            #pragma unroll
            for (int v = 0; v < 4; v++) acc[mi][ni][v] = 0.0f;

    sg_issue(sm, 0, Ahi, Alo, Bhi, Blo, bm, bn, K, tid);
    sg_issue(sm, 1, Ahi, Alo, Bhi, Blo, bm, bn, K, tid);

    const int ar = wm * 32 + (lane >> 2);
    const int bc = wn * 64 + (lane >> 2);
    const int q  = lane & 3;

    #pragma unroll 1
    for (int ch = 0; ch < NC; ch++) {
        if (ch == NC - 1) cp_wait0(); else cp_wait1();
        __syncthreads();
        if (ch + 2 < NC) sg_issue(sm, ch + 2, Ahi, Alo, Bhi, Blo, bm, bn, K, tid);
        const uint32_t* Ah = (const uint32_t*)(sm + (ch % 3) * SG_STAGE);
        const uint32_t* Al = Ah + SG_HALF / 4;
        const uint32_t* Bh = Ah + 2 * SG_HALF / 4;
        const uint32_t* Bl = Ah + 3 * SG_HALF / 4;
        #pragma unroll
        for (int kk = 0; kk < 4; kk++) {
            const int kb = kk * 8 + q;
            uint32_t ah[2][4], al[2][4], bh[8][2], bl[8][2];
            #pragma unroll
            for (int mi = 0; mi < 2; mi++) {
                const int r0 = (ar + mi * 16) * SG_STRIDE;
                const int r8 = (ar + mi * 16 + 8) * SG_STRIDE;
                ah[mi][0] = Ah[r0 + kb]; ah[mi][1] = Ah[r8 + kb];
                ah[mi][2] = Ah[r0 + kb + 4]; ah[mi][3] = Ah[r8 + kb + 4];
                al[mi][0] = Al[r0 + kb]; al[mi][1] = Al[r8 + kb];
                al[mi][2] = Al[r0 + kb + 4]; al[mi][3] = Al[r8 + kb + 4];
            }
            #pragma unroll
            for (int ni = 0; ni < 8; ni++) {
                const int rB = (bc + ni * 8) * SG_STRIDE;
                bh[ni][0] = Bh[rB + kb]; bh[ni][1] = Bh[rB + kb + 4];
                bl[ni][0] = Bl[rB + kb]; bl[ni][1] = Bl[rB + kb + 4];
            }
            #pragma unroll
            for (int mi = 0; mi < 2; mi++)
                #pragma unroll
                for (int ni = 0; ni < 8; ni++) {
                    mma8(acc[mi][ni], ah[mi], bl[ni]);
                    mma8(acc[mi][ni], al[mi], bh[ni]);
                    mma8(acc[mi][ni], ah[mi], bh[ni]);
                }
        }
    }
    __syncthreads();

    {
        float* gs = (float*)sm;
        const int grow = wm * 32 + (lane >> 2);
        const int gcol = wn * 64 + ((lane & 3) << 1);
        #pragma unroll
        for (int mi = 0; mi < 2; mi++)
            #pragma unroll
            for (int ni = 0; ni < 8; ni++) {
                int r = grow + mi * 16, cc = gcol + ni * 8;
                gs[r * SG_GS + cc]           = acc[mi][ni][0];
                gs[r * SG_GS + cc + 1]       = acc[mi][ni][1];
                gs[(r + 8) * SG_GS + cc]     = acc[mi][ni][2];
                gs[(r + 8) * SG_GS + cc + 1] = acc[mi][ni][3];
            }
    }
    __syncthreads();

    const float* gs = (const float*)sm;
    #pragma unroll
    for (int i = 0; i < 16; i++) {
        int row = i * 8 + wid;
        #pragma unroll
        for (int cc = 0; cc < 4; cc++) {
            int col = cc * 32 + lane;
            float v = gs[row * SG_GS + col] + bias[bn + col];
            if (relu) v = fmaxf(v, 0.0f);
            size_t o = (size_t)(bm + row) * N + bn + col;
            if (Clo) {
                float h = f2tf_f(v);
                Chi[o] = h;
                Clo[o] = f2tf_f(v - h);
            } else if (out16) {
                ((__half*)Chi)[o] = __float2half(v);
            } else {
                Chi[o] = v;
            }
        }
    }
}

// ===== fp16 LSTM step v3: 512 threads, 256x128 tile, register cell epilogue ==
// gates cols n' = 4*jloc + g (gate-interleaved within each jb tile).
// 2-stage cp.async (A+B), xp slice (fp16, row-major) streamed alongside.
// shfl.xor(1) pair-exchange -> full LSTM cell per thread, no gate staging.
#define SH_W     36                        // words per staged row (72 halves)
#define ST_A     (256 * SH_W * 4)          // 36864
#define ST_B     (128 * SH_W * 4)          // 18432
#define ST_STAGE (ST_A + ST_B)             // 55296 ; 2 stages = 110592
#define XP_OFF   (2 * ST_STAGE)            // 110592
#define XP_STRIDE 136                      // halves per xp row: 272 B = 17x16 (cp.async-aligned)
#define ST_SMEM  (XP_OFF + 256 * XP_STRIDE * 2)   // 180224
// hs (fp32 256x33 = 33792 B) aliases stage region (offset 0)

__device__ __forceinline__ void xp_piece(uint32_t xpb, int p, int bm, int jbc, int tid) {
    // piece p: local cols [32p, 32p+32) for all 256 rows; 1024 cp16
    #pragma unroll
    for (int g2 = 0; g2 < 2; g2++) {
        int v = g2 * 512 + tid;             // 0..1023
        int row = v >> 2;                   // 0..255
        int seg = v & 3;                    // 8 halves each
        cp16(xpb + (uint32_t)(row * XP_STRIDE + p * 32 + seg * 8) * 2,
             g_xpp + (size_t)(bm + row) * 1024 + jbc * 4 + p * 32 + seg * 8);
    }
}

__device__ __forceinline__ void st_issue(char* sm, int st, int bm, int bBase,
                                         int jbc, int tid)
{
    uint32_t base = smem_u32(sm + (st & 1) * ST_STAGE);
    const int k0 = st * 64;                       // halves
    const int srow = tid >> 3;                    // 0..63
    const int skw  = (tid & 7) << 2;              // word offset (8 halves each)
    #pragma unroll
    for (int i = 0; i < 4; i++) {
        int row = i * 64 + srow;
        cp16(base + (uint32_t)(row * SH_W + skw) * 4,
             g_ht + (size_t)(bm + row) * HID + k0 + skw * 2);
    }
    #pragma unroll
    for (int i = 0; i < 2; i++) {
        int row = i * 64 + srow;
        cp16(base + ST_A + (uint32_t)(row * SH_W + skw) * 4,
             g_whhc + (size_t)(bBase + row) * HID + k0 + skw * 2);
    }
    xp_piece(smem_u32(sm + XP_OFF), st, bm, jbc, tid);
    cp_commit();
}

__global__ void __launch_bounds__(512, 1)
lstm_step(float* __restrict__ out, int t)
{
    extern __shared__ char sm[];
    const int tid  = threadIdx.x;
    const int wid  = tid >> 5;
    const int lane = tid & 31;
    const int wm   = wid & 7, wn = wid >> 3;   // 8 x 2 warp grid (32x64 tiles)
    const int bm   = blockIdx.y * 256;
    const int jbc  = blockIdx.x * 32;          // hidden col base
    const int bBase = blockIdx.x * 128;        // g_whhc row base
    const int r    = lane >> 2;
    const int q    = lane & 3;
    const int odd  = q & 1;

    float acc[2][8][4];
    #pragma unroll
    for (int mi = 0; mi < 2; mi++)
        #pragma unroll
        for (int ni = 0; ni < 8; ni++)
            #pragma unroll
            for (int v = 0; v < 4; v++) acc[mi][ni][v] = 0.0f;

    if (t > 0) {
        st_issue(sm, 0, bm, bBase, jbc, tid);
        st_issue(sm, 1, bm, bBase, jbc, tid);

        const int ar = wm * 32 + r;
        const int bc = wn * 64 + r;

        #pragma unroll 1
        for (int ch = 0; ch < 4; ch++) {
            if (ch == 3) cp_wait0(); else cp_wait1();
            __syncthreads();
            const uint32_t* As = (const uint32_t*)(sm + (ch & 1) * ST_STAGE);
            const uint32_t* Bs = As + ST_A / 4;
            #pragma unroll
            for (int ks = 0; ks < 4; ks++) {
                const int kb = ks * 8 + q;
                uint32_t a[2][4], b[8][2];
                #pragma unroll
                for (int mi = 0; mi < 2; mi++) {
                    const int r0 = (ar + mi * 16) * SH_W;
                    const int r8 = (ar + mi * 16 + 8) * SH_W;
                    a[mi][0] = As[r0 + kb];
                    a[mi][1] = As[r8 + kb];
                    a[mi][2] = As[r0 + kb + 4];
                    a[mi][3] = As[r8 + kb + 4];
                }
                #pragma unroll
                for (int ni = 0; ni < 8; ni++) {
                    const int rB = (bc + ni * 8) * SH_W;
                    b[ni][0] = Bs[rB + kb];
                    b[ni][1] = Bs[rB + kb + 4];
                }
                #pragma unroll
                for (int mi = 0; mi < 2; mi++)
                    #pragma unroll
                    for (int ni = 0; ni < 8; ni++)
                        mma16(acc[mi][ni], a[mi], b[ni]);
            }
            __syncthreads();
            if (ch + 2 < 4) st_issue(sm, ch + 2, bm, bBase, jbc, tid);
        }
    } else {
        uint32_t xpb = smem_u32(sm + XP_OFF);
        #pragma unroll
        for (int p = 0; p < 4; p++) xp_piece(xpb, p, bm, jbc, tid);
        cp_commit(); cp_wait0();
        __syncthreads();
    }

    // ---------------- register LSTM cell epilogue (shfl pair-exchange) ------
    const __half* xps = (const __half*)(sm + XP_OFF);
    float* hs = (float*)sm;   // aliases stage region (all stage reads done)

    #pragma unroll
    for (int mi = 0; mi < 2; mi++) {
        const int rowloc = wm * 32 + 16 * mi + r + 8 * odd;
        float cpv[8];
        if (t > 0) {
            #pragma unroll
            for (int ni = 0; ni < 8; ni++) {
                int jl = wn * 16 + 2 * ni + (q >> 1);
                cpv[ni] = g_c[(size_t)(jbc + jl) * BATCH + bm + rowloc];
            }
        } else {
            #pragma unroll
            for (int ni = 0; ni < 8; ni++) cpv[ni] = 0.0f;
        }
        #pragma unroll
        for (int ni = 0; ni < 8; ni++) {
            float t0 = odd ? acc[mi][ni][0] : acc[mi][ni][2];
            float t1 = odd ? acc[mi][ni][1] : acc[mi][ni][3];
            float e0 = __shfl_xor_sync(0xffffffffu, t0, 1);
            float e1 = __shfl_xor_sync(0xffffffffu, t1, 1);
            float gi, gf, gg, go;
            if (!odd) { gi = acc[mi][ni][0]; gf = acc[mi][ni][1]; gg = e0; go = e1; }
            else      { gi = e0; gf = e1; gg = acc[mi][ni][2]; go = acc[mi][ni][3]; }
            const int jl = wn * 16 + 2 * ni + (q >> 1);
            uint2 xv = *(const uint2*)(xps + rowloc * XP_STRIDE + 4 * jl);
            __half2 x01 = *(__half2*)&xv.x;
            __half2 x23 = *(__half2*)&xv.y;
            gi += __low2float(x01);  gf += __high2float(x01);
            gg += __low2float(x23);  go += __high2float(x23);
            float vi = sigmoidf_fast(gi);
            float vf = sigmoidf_fast(gf);
            float vg = tanhf_fast(gg);
            float vo = sigmoidf_fast(go);
            float cn = vf * cpv[ni] + vi * vg;
            g_c[(size_t)(jbc + jl) * BATCH + bm + rowloc] = cn;
            hs[rowloc * 33 + jl] = vo * tanhf_fast(cn);
        }
    }
    __syncthreads();

    // ---- coalesced h writes: out (fp32 strided) + g_ht (fp16 compact) ----
    #pragma unroll
    for (int i = 0; i < 16; i++) {
        int row = i * 16 + wid;
        float v = hs[row * 33 + lane];
        out[(size_t)(bm + row) * HSTR + (size_t)t * HID + jbc + lane] = v;
        g_ht[(size_t)(bm + row) * HID + jbc + lane] = __float2half(v);
    }
}

// ---------------- launch ----------------
extern "C" void kernel_launch(void* const* d_in, const int* in_sizes, int n_in,
                              void* d_out, int out_size)
{
    const float* zs  = (const float*)d_in[0];
    const float* W1  = (const float*)d_in[1];
    const float* b1  = (const float*)d_in[2];
    const float* W2  = (const float*)d_in[3];
    const float* b2  = (const float*)d_in[4];
    const float* W3  = (const float*)d_in[5];
    const float* b3  = (const float*)d_in[6];
    const float* Wih = (const float*)d_in[7];
    const float* Whh = (const float*)d_in[8];
    const float* bih = (const float*)d_in[9];
    const float* bhh = (const float*)d_in[10];
    float* out = (float*)d_out;

    float *xhi, *xlo, *w1h, *w1l, *w2h, *w2l, *w3h, *w3l, *wihh, *wihl, *biasp;
    float *h1h, *h1l, *h2h, *h2l, *z1h, *z1l;
    void  *xpp;
    cudaGetSymbolAddress((void**)&xhi,   g_xhi);
    cudaGetSymbolAddress((void**)&xlo,   g_xlo);
    cudaGetSymbolAddress((void**)&w1h,   g_w1h);
    cudaGetSymbolAddress((void**)&w1l,   g_w1l);
    cudaGetSymbolAddress((void**)&w2h,   g_w2h);
    cudaGetSymbolAddress((void**)&w2l,   g_w2l);
    cudaGetSymbolAddress((void**)&w3h,   g_w3h);
    cudaGetSymbolAddress((void**)&w3l,   g_w3l);
    cudaGetSymbolAddress((void**)&wihh,  g_wihh);
    cudaGetSymbolAddress((void**)&wihl,  g_wihl);
    cudaGetSymbolAddress((void**)&biasp, g_biasp);
    cudaGetSymbolAddress((void**)&h1h,   g_h1h);
    cudaGetSymbolAddress((void**)&h1l,   g_h1l);
    cudaGetSymbolAddress((void**)&h2h,   g_h2h);
    cudaGetSymbolAddress((void**)&h2l,   g_h2l);
    cudaGetSymbolAddress((void**)&z1h,   g_z1h);
    cudaGetSymbolAddress((void**)&z1l,   g_z1l);
    cudaGetSymbolAddress(&xpp,           g_xpp);

    cudaFuncSetAttribute(mma_gemm_split,
                         cudaFuncAttributeMaxDynamicSharedMemorySize, SG_SMEM);
    cudaFuncSetAttribute(lstm_step,
                         cudaFuncAttributeMaxDynamicSharedMemorySize, ST_SMEM);

    // setup (no init_state needed: g_ht/g_c written at t=0 before any read)
    conv_all<<<5248, 256>>>(zs, W1, W2, W3);
    conv_wih_p<<<1024, 128>>>(Wih, bih, bhh);
    conv_whh_p<<<1024, 256>>>(Whh);

    // MLP (split-tf32, fp32-grade accuracy)
    mma_gemm_split<<<dim3(4, 32), 256, SG_SMEM>>>(xhi, xlo, w1h, w1l, b1,
                                                  h1h, h1l, BATCH, 512, 256, 1, 0);
    mma_gemm_split<<<dim3(2, 32), 256, SG_SMEM>>>(h1h, h1l, w2h, w2l, b2,
                                                  h2h, h2l, BATCH, 256, 512, 1, 0);
    mma_gemm_split<<<dim3(1, 32), 256, SG_SMEM>>>(h2h, h2l, w3h, w3l, b3,
                                                  z1h, z1l, BATCH, 128, 256, 0, 0);
    // x_part fp16 row-major [4096][1024], col = 4j+g (biases folded)
    mma_gemm_split<<<dim3(8, 32), 256, SG_SMEM>>>(z1h, z1l, wihh, wihl, biasp,
                                                  (float*)xpp, nullptr,
                                                  BATCH, 1024, 128, 0, 1);

    // 50 fp16 tensor-core LSTM steps (single wave: 8 x 16 = 128 CTAs)
    for (int t = 0; t < T_STEPS; t++)
        lstm_step<<<dim3(8, 16), 512, ST_SMEM>>>(out, t);
}